// round 9
// baseline (speedup 1.0000x reference)
#include <cuda_runtime.h>
#include <cuda_bf16.h>
#include <math.h>

// Problem shape (fixed by setup_inputs)
#define N     2048
#define C     256
#define NCLS  8
#define KSEL  20
#define MAXC  384      // class size bound; tiles cover 6*64=384
#define EPS   1e-6f

typedef unsigned long long u64;

// Scratch (static __device__ — no allocations)
// g_D layout: [4 channel-quarters][N rows (original index)][MAXC positions]
__device__ float g_D[4ull * N * MAXC];
__device__ int   g_orderC[NCLS * MAXC];   // per-class member lists (original indices)
__device__ int   g_cntC[NCLS];
__device__ float g_partial[256];
__device__ unsigned int g_counter;

__device__ __forceinline__ float finf() { return __int_as_float(0x7f800000); }

__device__ __forceinline__ u64 addx2(u64 a, u64 b) {
    u64 r;
    asm("add.rn.f32x2 %0, %1, %2;" : "=l"(r) : "l"(a), "l"(b));
    return r;
}

// ---------------------------------------------------------------------------
// Kernel 1: class-blocked pairwise L1 distance, packed f32x2, channel-QUARTER
// split. BANK-CONFLICT-FREE smem layout:
//   - rows padded to 66 (528B stride, 16B-aligned for A's LDS.128)
//   - each thread's 4 j-columns strided by 16 -> B loads are 4x LDS.64 at
//     lane-consecutive addresses (1 wavefront, 0 conflicts)
//   - staging uses lane-consecutive columns (lr = t&63) -> STS conflict-free
// Grid: 1152 = 4 quarters x (8 classes x 36 tiles), 5x5 working region first.
// ---------------------------------------------------------------------------
#define TB 64
#define KC 64      // channels per chunk == quarter size (32 packed pairs)
#define PADTB 66   // padded row length (528 bytes, multiple of 16)

__global__ __launch_bounds__(256, 3)
void dist_kernel(const float* __restrict__ feat, const int* __restrict__ target) {
    int bid = blockIdx.x;
    if (bid == 0 && threadIdx.x == 0) g_counter = 0u;   // reset for topk

    int cs  = bid / 288;               // channel quarter 0..3
    int b   = bid - cs * 288;
    int cls, x, y;
    if (b < 200) {                      // 5x5 working region first
        cls = b / 25; int r = b % 25; x = r % 5; y = r / 5;
    } else {                            // 6x6 fringe (x==5 or y==5)
        int e = b - 200; cls = e / 11; int r = e % 11;
        if (r < 6) { x = 5; y = r; } else { x = r - 6; y = 5; }
    }

    __shared__ __align__(16) float As2[KC / 2][PADTB][2];   // (a + eps), pair packed
    __shared__ __align__(16) float Bs2[KC / 2][PADTB][2];   // (-b), pair packed
    __shared__ __align__(16) int   list[MAXC];
    __shared__ int   s_wofs[8];
    __shared__ int   s_cnt;

    int t    = threadIdx.x;
    int lane = t & 31;
    int w    = t >> 5;

    // ---- cheap count first: early-exit for non-working tiles ----
    int4 t0 = *(const int4*)(target + t * 8);
    int4 t1 = *(const int4*)(target + t * 8 + 4);
    int tg[8] = {t0.x, t0.y, t0.z, t0.w, t1.x, t1.y, t1.z, t1.w};
    int mcount = 0;
#pragma unroll
    for (int u = 0; u < 8; u++) mcount += (tg[u] == cls);

    int red = mcount;
#pragma unroll
    for (int o = 16; o > 0; o >>= 1) red += __shfl_down_sync(0xffffffffu, red, o);
    if (lane == 0) s_wofs[w] = red;
    __syncthreads();
    if (t == 0) {
        int acc = 0;
#pragma unroll
        for (int ww = 0; ww < 8; ww++) acc += s_wofs[ww];
        s_cnt = acc;
    }
    __syncthreads();
    int cnt = min(s_cnt, MAXC);

    int ti0 = y * TB;
    int tj0 = x * TB;
    if (ti0 >= cnt || tj0 >= cnt) return;   // publishers (x=0,y=0) always pass

    // ---- full stable compaction (working blocks only) ----
    int incl = mcount;
#pragma unroll
    for (int o = 1; o < 32; o <<= 1) {
        int v = __shfl_up_sync(0xffffffffu, incl, o);
        if (lane >= o) incl += v;
    }
    if (lane == 31) s_wofs[w] = incl;
    __syncthreads();
    if (t == 0) {
        int acc = 0;
#pragma unroll
        for (int ww = 0; ww < 8; ww++) { int v = s_wofs[ww]; s_wofs[ww] = acc; acc += v; }
    }
    __syncthreads();
    int base = s_wofs[w] + incl - mcount;   // exclusive prefix for this thread
#pragma unroll
    for (int u = 0; u < 8; u++) {
        if (tg[u] == cls && base < MAXC) { list[base] = t * 8 + u; base++; }
    }
    __syncthreads();
    for (int p = cnt + t; p < MAXC; p += 256) list[p] = 0;   // safe padding
    __syncthreads();

    // publisher blocks export the list for topk (one block per class, cs==0)
    if (cs == 0 && x == 0 && y == 0) {
        if (t == 0) g_cntC[cls] = cnt;
        for (int p = t; p < cnt; p += 256) g_orderC[cls * MAXC + p] = list[p];
    }

    // ---- staging: thread t fills column lr (lane-consecutive), 16 channels ----
    {
        int lr = t & 63;
        int lc = (t >> 6) * 16;       // 0,16,32,48
        int gi = ti0 + lr, gj = tj0 + lr;
        const float* arow = feat + (size_t)list[min(gi, MAXC - 1)] * C;
        const float* brow = feat + (size_t)list[min(gj, MAXC - 1)] * C;
        int cc = cs * 64 + lc;
        int p0 = lc >> 1;
#pragma unroll
        for (int q = 0; q < 4; q++) {
            float4 pa = *(const float4*)(arow + cc + q * 4);
            float4 pb = *(const float4*)(brow + cc + q * 4);
            *(float2*)&As2[p0 + 2 * q + 0][lr][0] = make_float2(pa.x + EPS, pa.y + EPS);
            *(float2*)&As2[p0 + 2 * q + 1][lr][0] = make_float2(pa.z + EPS, pa.w + EPS);
            *(float2*)&Bs2[p0 + 2 * q + 0][lr][0] = make_float2(-pb.x, -pb.y);
            *(float2*)&Bs2[p0 + 2 * q + 1][lr][0] = make_float2(-pb.z, -pb.w);
        }
    }
    __syncthreads();   // the ONLY mainloop barrier

    int tx = t & 15;      // j columns: tx + 16c (strided -> conflict-free LDS.64)
    int ty = t >> 4;      // i rows: ty*4 + ii (contiguous -> broadcast LDS.128)

    u64 acc2[16];
#pragma unroll
    for (int q = 0; q < 16; q++) acc2[q] = 0ull;

#pragma unroll
    for (int kk2 = 0; kk2 < KC / 2; kk2++) {
        ulonglong2 aL = *(const ulonglong2*)&As2[kk2][ty * 4][0];
        ulonglong2 aH = *(const ulonglong2*)&As2[kk2][ty * 4 + 2][0];
        u64 a2[4] = {aL.x, aL.y, aH.x, aH.y};
        u64 b2[4];
#pragma unroll
        for (int c = 0; c < 4; c++)
            b2[c] = *(const u64*)&Bs2[kk2][tx + c * 16][0];
#pragma unroll
        for (int ii = 0; ii < 4; ii++)
#pragma unroll
            for (int c = 0; c < 4; c++) {
                u64 d = addx2(a2[ii], b2[c]);           // a + eps - b
                d &= 0x7FFFFFFF7FFFFFFFull;             // packed |.|
                acc2[ii * 4 + c] = addx2(acc2[ii * 4 + c], d);
            }
    }

    float* dq = g_D + (size_t)cs * N * MAXC;
#pragma unroll
    for (int ii = 0; ii < 4; ii++) {
        int ti = ti0 + ty * 4 + ii;
        if (ti >= cnt) continue;
        float* dr = dq + (size_t)list[ti] * MAXC + tj0;
#pragma unroll
        for (int c = 0; c < 4; c++) {
            u64 a = acc2[ii * 4 + c];
            float lo = __uint_as_float((unsigned)(a & 0xFFFFFFFFull));
            float hi = __uint_as_float((unsigned)(a >> 32));
            int tj = tj0 + tx + c * 16;
            dr[tx + c * 16] = (ti == tj) ? finf() : (lo + hi);
        }
    }
}

// ---------------------------------------------------------------------------
// Kernel 2: fused top-K + neighbor MSE + CE + final reduction (last block).
// One warp per row. EXACT Round-8 structure (measured 14.5us).
// ---------------------------------------------------------------------------
__global__ __launch_bounds__(256, 2)
void topk_loss_kernel(const float* __restrict__ feat,
                      const float* __restrict__ scores,
                      const int* __restrict__ target,
                      float* __restrict__ out) {
    __shared__ float s_part[8];
    __shared__ bool  s_last;

    int warp = threadIdx.x >> 5;
    int lane = threadIdx.x & 31;
    int i = blockIdx.x * 8 + warp;

    int cls = target[i];
    int cnt = min(g_cntC[cls], MAXC);
    const int* order = g_orderC + cls * MAXC;
    int m = min(cnt - 1, KSEL);

    float rowloss = 0.f;
    if (m > 0) {
        const float* d0 = g_D + (size_t)i * MAXC;
        const float* d1 = g_D + (size_t)(N + i) * MAXC;
        const float* d2 = g_D + (size_t)(2 * N + i) * MAXC;
        const float* d3 = g_D + (size_t)(3 * N + i) * MAXC;

        // packed keys: high 23 bits of distance | 9-bit position
        unsigned v[12];
#pragma unroll
        for (int s = 0; s < 12; s++) {
            int p = s * 32 + lane;
            if (p < cnt) {
                float d = (d0[p] + d1[p]) + (d2[p] + d3[p]);
                v[s] = (__float_as_uint(d) & 0xFFFFFE00u) | (unsigned)p;
            } else {
                v[s] = 0xFFFFFFFFu;
            }
        }

        unsigned mypos = 0;
#pragma unroll
        for (int r = 0; r < 10; r++) {
            // local two smallest of 12 slots
            unsigned k1 = 0xFFFFFFFFu, k2 = 0xFFFFFFFFu;
#pragma unroll
            for (int s = 0; s < 12; s++) {
                unsigned xv = v[s];
                unsigned nk2 = min(k2, max(k1, xv));
                k1 = min(k1, xv);
                k2 = nk2;
            }
            // warp-wide two smallest
#pragma unroll
            for (int o = 16; o > 0; o >>= 1) {
                unsigned p1 = __shfl_down_sync(0xffffffffu, k1, o);
                unsigned p2 = __shfl_down_sync(0xffffffffu, k2, o);
                unsigned hi = max(k1, p1);
                k1 = min(k1, p1);
                k2 = min(hi, min(k2, p2));
            }
            unsigned w1 = __shfl_sync(0xffffffffu, k1, 0);
            unsigned w2 = __shfl_sync(0xffffffffu, k2, 0);
            if (lane == 2 * r)     mypos = w1 & 511u;
            if (lane == 2 * r + 1) mypos = w2 & 511u;
#pragma unroll
            for (int s = 0; s < 12; s++) {
                if (v[s] == w1 || v[s] == w2) v[s] = 0xFFFFFFFFu;
            }
        }

        // resolve neighbor original index per lane (20 parallel loads)
        unsigned cp = min(mypos, (unsigned)(MAXC - 1));
        int myj = order[cp];

        // MSE gather: lane owns 8 channels; pre-resolved j broadcast per k.
        float inv_m = 1.0f / (float)m;
        const float* xi = feat + (size_t)i * C + lane * 8;
        float4 x0 = *(const float4*)(xi);
        float4 x1 = *(const float4*)(xi + 4);
        float acc = 0.f;
#pragma unroll
        for (int k = 0; k < KSEL; k++) {
            bool valid = (k < m);
            int j = __shfl_sync(0xffffffffu, myj, k);
            const float* xj = feat + (size_t)j * C + lane * 8;
            float4 a0 = *(const float4*)(xj);
            float4 a1 = *(const float4*)(xj + 4);
            float s = 0.f, d;
            d = x0.x - a0.x * inv_m; s += d * d;
            d = x0.y - a0.y * inv_m; s += d * d;
            d = x0.z - a0.z * inv_m; s += d * d;
            d = x0.w - a0.w * inv_m; s += d * d;
            d = x1.x - a1.x * inv_m; s += d * d;
            d = x1.y - a1.y * inv_m; s += d * d;
            d = x1.z - a1.z * inv_m; s += d * d;
            d = x1.w - a1.w * inv_m; s += d * d;
            acc += valid ? s : 0.f;
        }
#pragma unroll
        for (int o = 16; o > 0; o >>= 1)
            acc += __shfl_down_sync(0xffffffffu, acc, o);
        rowloss = acc;
    }

    // per-row CE (lane 0), combine with lam term
    if (lane == 0) {
        float4 s0 = *(const float4*)(scores + (size_t)i * NCLS);
        float4 s1 = *(const float4*)(scores + (size_t)i * NCLS + 4);
        float sv[8] = {s0.x, s0.y, s0.z, s0.w, s1.x, s1.y, s1.z, s1.w};
        float mx = sv[0];
#pragma unroll
        for (int c = 1; c < 8; c++) mx = fmaxf(mx, sv[c]);
        float se = 0.f;
#pragma unroll
        for (int c = 0; c < 8; c++) se += __expf(sv[c] - mx);
        float ce = (mx + __logf(se)) - sv[cls];
        s_part[warp] = ce * (1.0f / (float)N) + 25.0f * rowloss;  // LAM*0.5 = 25
    }
    __syncthreads();

    if (threadIdx.x == 0) {
        float p = 0.f;
#pragma unroll
        for (int w = 0; w < 8; w++) p += s_part[w];
        g_partial[blockIdx.x] = p;
        __threadfence();
        unsigned int done = atomicAdd(&g_counter, 1u);
        s_last = (done == 255u);
    }
    __syncthreads();

    if (s_last) {
        __shared__ float sred[256];
        int t = threadIdx.x;
        sred[t] = g_partial[t];
        __syncthreads();
        for (int o = 128; o > 0; o >>= 1) {
            if (t < o) sred[t] += sred[t + o];
            __syncthreads();
        }
        if (t == 0) out[0] = sred[0];
    }
}

// ---------------------------------------------------------------------------
extern "C" void kernel_launch(void* const* d_in, const int* in_sizes, int n_in,
                              void* d_out, int out_size) {
    const float* feature = (const float*)d_in[0];   // [2048, 256]
    const float* scores  = (const float*)d_in[1];   // [2048, 8]
    const int*   target  = (const int*)d_in[2];     // [2048]
    float* out = (float*)d_out;

    dist_kernel<<<1152, 256>>>(feature, target);
    topk_loss_kernel<<<N / 8, 256>>>(feature, scores, target, out);
}

// round 10
// speedup vs baseline: 1.0407x; 1.0407x over previous
#include <cuda_runtime.h>
#include <cuda_bf16.h>
#include <math.h>

// Problem shape (fixed by setup_inputs)
#define N     2048
#define C     256
#define NCLS  8
#define KSEL  20
#define MAXC  384      // class size bound; tiles cover 6*64=384
#define EPS   1e-6f

typedef unsigned long long u64;

// Scratch (static __device__ — no allocations)
// g_D layout: [4 channel-quarters][N rows (original index)][MAXC positions]
__device__ float g_D[4ull * N * MAXC];
__device__ int   g_orderC[NCLS * MAXC];   // per-class member lists (original indices)
__device__ int   g_cntC[NCLS];
__device__ float g_partial[256];
__device__ unsigned int g_counter;

// triangle tile enumeration: x >= y, 6x6 -> 21 tiles; 5x5 triangle first
__device__ __constant__ int c_tx[21] = {0,1,1,2,2,2,3,3,3,3,4,4,4,4,4,5,5,5,5,5,5};
__device__ __constant__ int c_ty[21] = {0,0,1,0,1,2,0,1,2,3,0,1,2,3,4,0,1,2,3,4,5};

__device__ __forceinline__ float finf() { return __int_as_float(0x7f800000); }

__device__ __forceinline__ u64 addx2(u64 a, u64 b) {
    u64 r;
    asm("add.rn.f32x2 %0, %1, %2;" : "=l"(r) : "l"(a), "l"(b));
    return r;
}

// ---------------------------------------------------------------------------
// Kernel 0: class-grouping lists, ONE block, warp-shuffle vector scan.
// ---------------------------------------------------------------------------
__global__ __launch_bounds__(256, 1)
void perm_kernel(const int* __restrict__ target) {
    __shared__ int sc[8][NCLS];   // [warp][class] inclusive totals
    int t = threadIdx.x, lane = t & 31, w = t >> 5;
    if (t == 0) g_counter = 0u;

    int4 a = *(const int4*)(target + t * 8);
    int4 b = *(const int4*)(target + t * 8 + 4);
    int tg[8] = {a.x, a.y, a.z, a.w, b.x, b.y, b.z, b.w};
    int loc[NCLS];
#pragma unroll
    for (int c = 0; c < NCLS; c++) loc[c] = 0;
#pragma unroll
    for (int u = 0; u < 8; u++) loc[tg[u]]++;

    int incl[NCLS];
#pragma unroll
    for (int c = 0; c < NCLS; c++) {
        int v = loc[c];
#pragma unroll
        for (int o = 1; o < 32; o <<= 1) {
            int s = __shfl_up_sync(0xffffffffu, v, o);
            if (lane >= o) v += s;
        }
        incl[c] = v;
    }
    if (lane == 31) {
#pragma unroll
        for (int c = 0; c < NCLS; c++) sc[w][c] = incl[c];
    }
    __syncthreads();

    int wofs[NCLS], tot[NCLS];
#pragma unroll
    for (int c = 0; c < NCLS; c++) {
        int a0 = 0, tt = 0;
#pragma unroll
        for (int ww = 0; ww < 8; ww++) {
            int s = sc[ww][c];
            if (ww < w) a0 += s;
            tt += s;
        }
        wofs[c] = a0; tot[c] = tt;
    }

    int run[NCLS];
#pragma unroll
    for (int c = 0; c < NCLS; c++) run[c] = 0;
#pragma unroll
    for (int u = 0; u < 8; u++) {
        int c = tg[u];
        int pos = wofs[c] + (incl[c] - loc[c]) + run[c];
        if (pos < MAXC) g_orderC[c * MAXC + pos] = t * 8 + u;
        run[c]++;
    }
    if (t < NCLS) g_cntC[t] = min(tot[t], MAXC);

    // zero-pad each class list (safe row-0 fallback for clamped reads)
    for (int p = t; p < NCLS * MAXC; p += 256) {
        int c = p / MAXC, q = p - c * MAXC;
        if (q >= tot[c]) g_orderC[p] = 0;
    }
}

// ---------------------------------------------------------------------------
// Kernel 1: class-blocked pairwise L1 (NO eps -> symmetric), channel-quarter
// split, TRIANGLE tiles only (x >= y). Off-diagonal tiles mirror their result
// via an smem transpose into coalesced row writes.
// Grid: 672 = 4 quarters x 8 classes x 21 triangle tiles.
// ---------------------------------------------------------------------------
#define TB 64
#define KC 64      // channels per chunk == quarter size (32 packed pairs)
#define PADTB 66   // padded row length (528 bytes, multiple of 16)

__global__ __launch_bounds__(256, 3)
void dist_kernel(const float* __restrict__ feat) {
    int bid = blockIdx.x;
    int cs  = bid / 168;               // channel quarter 0..3
    int b   = bid - cs * 168;
    int cls = b / 21;
    int e   = b - cls * 21;
    int x = c_tx[e], y = c_ty[e];      // x >= y

    int cnt = min(g_cntC[cls], MAXC);
    int ti0 = y * TB;
    int tj0 = x * TB;
    if (ti0 >= cnt || tj0 >= cnt) return;

    const int* order = g_orderC + cls * MAXC;

    __shared__ __align__(16) float As2[KC / 2][PADTB][2];   // a, pair packed
    __shared__ __align__(16) float Bs2[KC / 2][PADTB][2];   // -b, pair packed

    int t = threadIdx.x;

    // ---- staging: thread t fills column lr, 16 channels ----
    {
        int lr = t & 63;
        int lc = (t >> 6) * 16;       // 0,16,32,48
        int gi = ti0 + lr, gj = tj0 + lr;
        const float* arow = feat + (size_t)order[min(gi, MAXC - 1)] * C;
        const float* brow = feat + (size_t)order[min(gj, MAXC - 1)] * C;
        int cc = cs * 64 + lc;
        int p0 = lc >> 1;
#pragma unroll
        for (int q = 0; q < 4; q++) {
            float4 pa = *(const float4*)(arow + cc + q * 4);
            float4 pb = *(const float4*)(brow + cc + q * 4);
            *(float2*)&As2[p0 + 2 * q + 0][lr][0] = make_float2(pa.x, pa.y);
            *(float2*)&As2[p0 + 2 * q + 1][lr][0] = make_float2(pa.z, pa.w);
            *(float2*)&Bs2[p0 + 2 * q + 0][lr][0] = make_float2(-pb.x, -pb.y);
            *(float2*)&Bs2[p0 + 2 * q + 1][lr][0] = make_float2(-pb.z, -pb.w);
        }
    }
    __syncthreads();

    int tx = t & 15;      // j columns: tx + 16c
    int ty = t >> 4;      // i rows: ty*4 + ii

    u64 acc2[16];
#pragma unroll
    for (int q = 0; q < 16; q++) acc2[q] = 0ull;

#pragma unroll
    for (int kk2 = 0; kk2 < KC / 2; kk2++) {
        ulonglong2 aL = *(const ulonglong2*)&As2[kk2][ty * 4][0];
        ulonglong2 aH = *(const ulonglong2*)&As2[kk2][ty * 4 + 2][0];
        u64 a2[4] = {aL.x, aL.y, aH.x, aH.y};
        u64 b2[4];
#pragma unroll
        for (int c = 0; c < 4; c++)
            b2[c] = *(const u64*)&Bs2[kk2][tx + c * 16][0];
#pragma unroll
        for (int ii = 0; ii < 4; ii++)
#pragma unroll
            for (int c = 0; c < 4; c++) {
                u64 d = addx2(a2[ii], b2[c]);           // a - b
                d &= 0x7FFFFFFF7FFFFFFFull;             // packed |.|
                acc2[ii * 4 + c] = addx2(acc2[ii * 4 + c], d);
            }
    }

    // unpack results
    float res[4][4];
#pragma unroll
    for (int ii = 0; ii < 4; ii++)
#pragma unroll
        for (int c = 0; c < 4; c++) {
            u64 a = acc2[ii * 4 + c];
            float lo = __uint_as_float((unsigned)(a & 0xFFFFFFFFull));
            float hi = __uint_as_float((unsigned)(a >> 32));
            res[ii][c] = lo + hi;
        }

    float* dq = g_D + (size_t)cs * N * MAXC;

    // direct store: D[order[ti]][tj0 + tx + 16c]
#pragma unroll
    for (int ii = 0; ii < 4; ii++) {
        int ti = ti0 + ty * 4 + ii;
        if (ti >= cnt) continue;
        float* dr = dq + (size_t)order[ti] * MAXC + tj0;
#pragma unroll
        for (int c = 0; c < 4; c++) {
            int tj = tj0 + tx + c * 16;
            dr[tx + c * 16] = (ti == tj) ? finf() : res[ii][c];
        }
    }

    // mirror store for off-diagonal tiles (transpose via smem alias of As2)
    if (x != y) {
        __syncthreads();   // mainloop reads done before overwriting As2
        float* tb = &As2[0][0][0];   // 64 x 65 floats (4160 <= 4224 available)
#pragma unroll
        for (int ii = 0; ii < 4; ii++)
#pragma unroll
            for (int c = 0; c < 4; c++)
                tb[(ty * 4 + ii) * 65 + tx + c * 16] = res[ii][c];
        __syncthreads();

        int j  = t & 63;
        int ic = (t >> 6) * 16;
        if (tj0 + j < cnt) {
            float* drj = dq + (size_t)order[tj0 + j] * MAXC + ti0 + ic;
#pragma unroll
            for (int q = 0; q < 4; q++) {
                float4 o;
                o.x = tb[(ic + 4 * q + 0) * 65 + j];
                o.y = tb[(ic + 4 * q + 1) * 65 + j];
                o.z = tb[(ic + 4 * q + 2) * 65 + j];
                o.w = tb[(ic + 4 * q + 3) * 65 + j];
                *(float4*)(drj + 4 * q) = o;
            }
        }
    }
}

// ---------------------------------------------------------------------------
// Kernel 2: fused top-K + neighbor MSE + CE + final reduction (last block).
// One warp per row. Measured-best R8 structure (14.5us), unchanged.
// ---------------------------------------------------------------------------
__global__ __launch_bounds__(256, 2)
void topk_loss_kernel(const float* __restrict__ feat,
                      const float* __restrict__ scores,
                      const int* __restrict__ target,
                      float* __restrict__ out) {
    __shared__ float s_part[8];
    __shared__ bool  s_last;

    int warp = threadIdx.x >> 5;
    int lane = threadIdx.x & 31;
    int i = blockIdx.x * 8 + warp;

    int cls = target[i];
    int cnt = min(g_cntC[cls], MAXC);
    const int* order = g_orderC + cls * MAXC;
    int m = min(cnt - 1, KSEL);

    float rowloss = 0.f;
    if (m > 0) {
        const float* d0 = g_D + (size_t)i * MAXC;
        const float* d1 = g_D + (size_t)(N + i) * MAXC;
        const float* d2 = g_D + (size_t)(2 * N + i) * MAXC;
        const float* d3 = g_D + (size_t)(3 * N + i) * MAXC;

        // packed keys: high 23 bits of distance | 9-bit position
        unsigned v[12];
#pragma unroll
        for (int s = 0; s < 12; s++) {
            int p = s * 32 + lane;
            if (p < cnt) {
                float d = (d0[p] + d1[p]) + (d2[p] + d3[p]);
                v[s] = (__float_as_uint(d) & 0xFFFFFE00u) | (unsigned)p;
            } else {
                v[s] = 0xFFFFFFFFu;
            }
        }

        unsigned mypos = 0;
#pragma unroll
        for (int r = 0; r < 10; r++) {
            unsigned k1 = 0xFFFFFFFFu, k2 = 0xFFFFFFFFu;
#pragma unroll
            for (int s = 0; s < 12; s++) {
                unsigned xv = v[s];
                unsigned nk2 = min(k2, max(k1, xv));
                k1 = min(k1, xv);
                k2 = nk2;
            }
#pragma unroll
            for (int o = 16; o > 0; o >>= 1) {
                unsigned p1 = __shfl_down_sync(0xffffffffu, k1, o);
                unsigned p2 = __shfl_down_sync(0xffffffffu, k2, o);
                unsigned hi = max(k1, p1);
                k1 = min(k1, p1);
                k2 = min(hi, min(k2, p2));
            }
            unsigned w1 = __shfl_sync(0xffffffffu, k1, 0);
            unsigned w2 = __shfl_sync(0xffffffffu, k2, 0);
            if (lane == 2 * r)     mypos = w1 & 511u;
            if (lane == 2 * r + 1) mypos = w2 & 511u;
#pragma unroll
            for (int s = 0; s < 12; s++) {
                if (v[s] == w1 || v[s] == w2) v[s] = 0xFFFFFFFFu;
            }
        }

        unsigned cp = min(mypos, (unsigned)(MAXC - 1));
        int myj = order[cp];

        float inv_m = 1.0f / (float)m;
        const float* xi = feat + (size_t)i * C + lane * 8;
        float4 x0 = *(const float4*)(xi);
        float4 x1 = *(const float4*)(xi + 4);
        float acc = 0.f;
#pragma unroll
        for (int k = 0; k < KSEL; k++) {
            bool valid = (k < m);
            int j = __shfl_sync(0xffffffffu, myj, k);
            const float* xj = feat + (size_t)j * C + lane * 8;
            float4 a0 = *(const float4*)(xj);
            float4 a1 = *(const float4*)(xj + 4);
            float s = 0.f, d;
            d = x0.x - a0.x * inv_m; s += d * d;
            d = x0.y - a0.y * inv_m; s += d * d;
            d = x0.z - a0.z * inv_m; s += d * d;
            d = x0.w - a0.w * inv_m; s += d * d;
            d = x1.x - a1.x * inv_m; s += d * d;
            d = x1.y - a1.y * inv_m; s += d * d;
            d = x1.z - a1.z * inv_m; s += d * d;
            d = x1.w - a1.w * inv_m; s += d * d;
            acc += valid ? s : 0.f;
        }
#pragma unroll
        for (int o = 16; o > 0; o >>= 1)
            acc += __shfl_down_sync(0xffffffffu, acc, o);
        rowloss = acc;
    }

    if (lane == 0) {
        float4 s0 = *(const float4*)(scores + (size_t)i * NCLS);
        float4 s1 = *(const float4*)(scores + (size_t)i * NCLS + 4);
        float sv[8] = {s0.x, s0.y, s0.z, s0.w, s1.x, s1.y, s1.z, s1.w};
        float mx = sv[0];
#pragma unroll
        for (int c = 1; c < 8; c++) mx = fmaxf(mx, sv[c]);
        float se = 0.f;
#pragma unroll
        for (int c = 0; c < 8; c++) se += __expf(sv[c] - mx);
        float ce = (mx + __logf(se)) - sv[cls];
        s_part[warp] = ce * (1.0f / (float)N) + 25.0f * rowloss;  // LAM*0.5 = 25
    }
    __syncthreads();

    if (threadIdx.x == 0) {
        float p = 0.f;
#pragma unroll
        for (int w = 0; w < 8; w++) p += s_part[w];
        g_partial[blockIdx.x] = p;
        __threadfence();
        unsigned int done = atomicAdd(&g_counter, 1u);
        s_last = (done == 255u);
    }
    __syncthreads();

    if (s_last) {
        __shared__ float sred[256];
        int t = threadIdx.x;
        sred[t] = g_partial[t];
        __syncthreads();
        for (int o = 128; o > 0; o >>= 1) {
            if (t < o) sred[t] += sred[t + o];
            __syncthreads();
        }
        if (t == 0) out[0] = sred[0];
    }
}

// ---------------------------------------------------------------------------
extern "C" void kernel_launch(void* const* d_in, const int* in_sizes, int n_in,
                              void* d_out, int out_size) {
    const float* feature = (const float*)d_in[0];   // [2048, 256]
    const float* scores  = (const float*)d_in[1];   // [2048, 8]
    const int*   target  = (const int*)d_in[2];     // [2048]
    float* out = (float*)d_out;

    perm_kernel<<<1, 256>>>(target);
    dist_kernel<<<672, 256>>>(feature);
    topk_loss_kernel<<<N / 8, 256>>>(feature, scores, target, out);
}

// round 11
// speedup vs baseline: 1.1974x; 1.1506x over previous
#include <cuda_runtime.h>
#include <cuda_bf16.h>
#include <math.h>

// Problem shape (fixed by setup_inputs)
#define N     2048
#define C     256
#define NCLS  8
#define KSEL  20
#define MAXC  384      // class size bound; tiles cover 6*64=384
#define EPS   1e-6f

typedef unsigned long long u64;

// Scratch (static __device__ — no allocations)
// g_D layout: [4 channel-quarters][N rows (original index)][MAXC positions]
__device__ float g_D[4ull * N * MAXC];
__device__ int   g_orderC[NCLS * MAXC];   // per-class member lists (original indices)
__device__ int   g_cntC[NCLS];
__device__ float g_partial[256];
__device__ unsigned int g_counter;

// triangle tile enumeration: x >= y, 6x6 -> 21 tiles
__device__ __constant__ int c_tx[21] = {0,1,1,2,2,2,3,3,3,3,4,4,4,4,4,5,5,5,5,5,5};
__device__ __constant__ int c_ty[21] = {0,0,1,0,1,2,0,1,2,3,0,1,2,3,4,0,1,2,3,4,5};

__device__ __forceinline__ float finf() { return __int_as_float(0x7f800000); }

__device__ __forceinline__ u64 addx2(u64 a, u64 b) {
    u64 r;
    asm("add.rn.f32x2 %0, %1, %2;" : "=l"(r) : "l"(a), "l"(b));
    return r;
}

// ---------------------------------------------------------------------------
// Kernel 1: class-blocked pairwise L1 (no eps -> symmetric), channel-quarter
// split, TRIANGLE tiles only (x >= y), mirror store via smem transpose.
// Per-block INLINE class-list rebuild (measured free in R8; kills the 8.5us
// single-block perm kernel). Publisher blocks (cs==0, e==0) export lists.
// Grid: 672 = 4 quarters x 8 classes x 21 triangle tiles.
// ---------------------------------------------------------------------------
#define TB 64
#define KC 64      // channels per chunk == quarter size (32 packed pairs)
#define PADTB 66   // padded row length (528 bytes, multiple of 16)

__global__ __launch_bounds__(256, 3)
void dist_kernel(const float* __restrict__ feat, const int* __restrict__ target) {
    int bid = blockIdx.x;
    if (bid == 0 && threadIdx.x == 0) g_counter = 0u;   // reset for topk

    int cs  = bid / 168;               // channel quarter 0..3
    int b   = bid - cs * 168;
    int cls = b / 21;
    int e   = b - cls * 21;
    int x = c_tx[e], y = c_ty[e];      // x >= y

    __shared__ __align__(16) float As2[KC / 2][PADTB][2];   // a, pair packed
    __shared__ __align__(16) float Bs2[KC / 2][PADTB][2];   // -b, pair packed
    __shared__ __align__(16) int   list[MAXC];
    __shared__ int   s_wofs[8];
    __shared__ int   s_cnt;

    int t    = threadIdx.x;
    int lane = t & 31;
    int w    = t >> 5;

    // ---- cheap count first: early-exit for non-working tiles ----
    int4 t0 = *(const int4*)(target + t * 8);
    int4 t1 = *(const int4*)(target + t * 8 + 4);
    int tg[8] = {t0.x, t0.y, t0.z, t0.w, t1.x, t1.y, t1.z, t1.w};
    int mcount = 0;
#pragma unroll
    for (int u = 0; u < 8; u++) mcount += (tg[u] == cls);

    int red = mcount;
#pragma unroll
    for (int o = 16; o > 0; o >>= 1) red += __shfl_down_sync(0xffffffffu, red, o);
    if (lane == 0) s_wofs[w] = red;
    __syncthreads();
    if (t == 0) {
        int acc = 0;
#pragma unroll
        for (int ww = 0; ww < 8; ww++) acc += s_wofs[ww];
        s_cnt = acc;
    }
    __syncthreads();
    int cnt = min(s_cnt, MAXC);

    int ti0 = y * TB;
    int tj0 = x * TB;
    if (ti0 >= cnt || tj0 >= cnt) return;   // publishers (e==0) always pass

    // ---- full stable compaction (working blocks only) ----
    int incl = mcount;
#pragma unroll
    for (int o = 1; o < 32; o <<= 1) {
        int v = __shfl_up_sync(0xffffffffu, incl, o);
        if (lane >= o) incl += v;
    }
    if (lane == 31) s_wofs[w] = incl;
    __syncthreads();
    if (t == 0) {
        int acc = 0;
#pragma unroll
        for (int ww = 0; ww < 8; ww++) { int v = s_wofs[ww]; s_wofs[ww] = acc; acc += v; }
    }
    __syncthreads();
    int base = s_wofs[w] + incl - mcount;   // exclusive prefix for this thread
#pragma unroll
    for (int u = 0; u < 8; u++) {
        if (tg[u] == cls && base < MAXC) { list[base] = t * 8 + u; base++; }
    }
    __syncthreads();
    for (int p = cnt + t; p < MAXC; p += 256) list[p] = 0;   // safe padding
    __syncthreads();

    // publisher blocks export the list for topk (one block per class, cs==0)
    if (cs == 0 && e == 0) {
        if (t == 0) g_cntC[cls] = cnt;
        for (int p = t; p < MAXC; p += 256) g_orderC[cls * MAXC + p] = list[p];
    }

    // ---- staging: thread t fills column lr, 16 channels ----
    {
        int lr = t & 63;
        int lc = (t >> 6) * 16;       // 0,16,32,48
        int gi = ti0 + lr, gj = tj0 + lr;
        const float* arow = feat + (size_t)list[min(gi, MAXC - 1)] * C;
        const float* brow = feat + (size_t)list[min(gj, MAXC - 1)] * C;
        int cc = cs * 64 + lc;
        int p0 = lc >> 1;
#pragma unroll
        for (int q = 0; q < 4; q++) {
            float4 pa = *(const float4*)(arow + cc + q * 4);
            float4 pb = *(const float4*)(brow + cc + q * 4);
            *(float2*)&As2[p0 + 2 * q + 0][lr][0] = make_float2(pa.x, pa.y);
            *(float2*)&As2[p0 + 2 * q + 1][lr][0] = make_float2(pa.z, pa.w);
            *(float2*)&Bs2[p0 + 2 * q + 0][lr][0] = make_float2(-pb.x, -pb.y);
            *(float2*)&Bs2[p0 + 2 * q + 1][lr][0] = make_float2(-pb.z, -pb.w);
        }
    }
    __syncthreads();

    int tx = t & 15;      // j columns: tx + 16c
    int ty = t >> 4;      // i rows: ty*4 + ii

    u64 acc2[16];
#pragma unroll
    for (int q = 0; q < 16; q++) acc2[q] = 0ull;

#pragma unroll
    for (int kk2 = 0; kk2 < KC / 2; kk2++) {
        ulonglong2 aL = *(const ulonglong2*)&As2[kk2][ty * 4][0];
        ulonglong2 aH = *(const ulonglong2*)&As2[kk2][ty * 4 + 2][0];
        u64 a2[4] = {aL.x, aL.y, aH.x, aH.y};
        u64 b2[4];
#pragma unroll
        for (int c = 0; c < 4; c++)
            b2[c] = *(const u64*)&Bs2[kk2][tx + c * 16][0];
#pragma unroll
        for (int ii = 0; ii < 4; ii++)
#pragma unroll
            for (int c = 0; c < 4; c++) {
                u64 d = addx2(a2[ii], b2[c]);           // a - b
                d &= 0x7FFFFFFF7FFFFFFFull;             // packed |.|
                acc2[ii * 4 + c] = addx2(acc2[ii * 4 + c], d);
            }
    }

    // unpack results
    float res[4][4];
#pragma unroll
    for (int ii = 0; ii < 4; ii++)
#pragma unroll
        for (int c = 0; c < 4; c++) {
            u64 a = acc2[ii * 4 + c];
            float lo = __uint_as_float((unsigned)(a & 0xFFFFFFFFull));
            float hi = __uint_as_float((unsigned)(a >> 32));
            res[ii][c] = lo + hi;
        }

    float* dq = g_D + (size_t)cs * N * MAXC;

    // direct store: D[list[ti]][tj0 + tx + 16c]
#pragma unroll
    for (int ii = 0; ii < 4; ii++) {
        int ti = ti0 + ty * 4 + ii;
        if (ti >= cnt) continue;
        float* dr = dq + (size_t)list[ti] * MAXC + tj0;
#pragma unroll
        for (int c = 0; c < 4; c++) {
            int tj = tj0 + tx + c * 16;
            dr[tx + c * 16] = (ti == tj) ? finf() : res[ii][c];
        }
    }

    // mirror store for off-diagonal tiles (transpose via smem alias of As2)
    if (x != y) {
        __syncthreads();   // mainloop reads done before overwriting As2
        float* tb = &As2[0][0][0];   // 64 x 65 floats fits in As2
#pragma unroll
        for (int ii = 0; ii < 4; ii++)
#pragma unroll
            for (int c = 0; c < 4; c++)
                tb[(ty * 4 + ii) * 65 + tx + c * 16] = res[ii][c];
        __syncthreads();

        int j  = t & 63;
        int ic = (t >> 6) * 16;
        if (tj0 + j < cnt) {
            float* drj = dq + (size_t)list[tj0 + j] * MAXC + ti0 + ic;
#pragma unroll
            for (int q = 0; q < 4; q++) {
                float4 o;
                o.x = tb[(ic + 4 * q + 0) * 65 + j];
                o.y = tb[(ic + 4 * q + 1) * 65 + j];
                o.z = tb[(ic + 4 * q + 2) * 65 + j];
                o.w = tb[(ic + 4 * q + 3) * 65 + j];
                *(float4*)(drj + 4 * q) = o;
            }
        }
    }
}

// ---------------------------------------------------------------------------
// Kernel 2: fused top-K + neighbor MSE + CE + final reduction (last block).
// One warp per row. Measured-best structure (14.5us), unchanged.
// ---------------------------------------------------------------------------
__global__ __launch_bounds__(256, 2)
void topk_loss_kernel(const float* __restrict__ feat,
                      const float* __restrict__ scores,
                      const int* __restrict__ target,
                      float* __restrict__ out) {
    __shared__ float s_part[8];
    __shared__ bool  s_last;

    int warp = threadIdx.x >> 5;
    int lane = threadIdx.x & 31;
    int i = blockIdx.x * 8 + warp;

    int cls = target[i];
    int cnt = min(g_cntC[cls], MAXC);
    const int* order = g_orderC + cls * MAXC;
    int m = min(cnt - 1, KSEL);

    float rowloss = 0.f;
    if (m > 0) {
        const float* d0 = g_D + (size_t)i * MAXC;
        const float* d1 = g_D + (size_t)(N + i) * MAXC;
        const float* d2 = g_D + (size_t)(2 * N + i) * MAXC;
        const float* d3 = g_D + (size_t)(3 * N + i) * MAXC;

        // packed keys: high 23 bits of distance | 9-bit position
        unsigned v[12];
#pragma unroll
        for (int s = 0; s < 12; s++) {
            int p = s * 32 + lane;
            if (p < cnt) {
                float d = (d0[p] + d1[p]) + (d2[p] + d3[p]);
                v[s] = (__float_as_uint(d) & 0xFFFFFE00u) | (unsigned)p;
            } else {
                v[s] = 0xFFFFFFFFu;
            }
        }

        unsigned mypos = 0;
#pragma unroll
        for (int r = 0; r < 10; r++) {
            unsigned k1 = 0xFFFFFFFFu, k2 = 0xFFFFFFFFu;
#pragma unroll
            for (int s = 0; s < 12; s++) {
                unsigned xv = v[s];
                unsigned nk2 = min(k2, max(k1, xv));
                k1 = min(k1, xv);
                k2 = nk2;
            }
#pragma unroll
            for (int o = 16; o > 0; o >>= 1) {
                unsigned p1 = __shfl_down_sync(0xffffffffu, k1, o);
                unsigned p2 = __shfl_down_sync(0xffffffffu, k2, o);
                unsigned hi = max(k1, p1);
                k1 = min(k1, p1);
                k2 = min(hi, min(k2, p2));
            }
            unsigned w1 = __shfl_sync(0xffffffffu, k1, 0);
            unsigned w2 = __shfl_sync(0xffffffffu, k2, 0);
            if (lane == 2 * r)     mypos = w1 & 511u;
            if (lane == 2 * r + 1) mypos = w2 & 511u;
#pragma unroll
            for (int s = 0; s < 12; s++) {
                if (v[s] == w1 || v[s] == w2) v[s] = 0xFFFFFFFFu;
            }
        }

        unsigned cp = min(mypos, (unsigned)(MAXC - 1));
        int myj = order[cp];

        float inv_m = 1.0f / (float)m;
        const float* xi = feat + (size_t)i * C + lane * 8;
        float4 x0 = *(const float4*)(xi);
        float4 x1 = *(const float4*)(xi + 4);
        float acc = 0.f;
#pragma unroll
        for (int k = 0; k < KSEL; k++) {
            bool valid = (k < m);
            int j = __shfl_sync(0xffffffffu, myj, k);
            const float* xj = feat + (size_t)j * C + lane * 8;
            float4 a0 = *(const float4*)(xj);
            float4 a1 = *(const float4*)(xj + 4);
            float s = 0.f, d;
            d = x0.x - a0.x * inv_m; s += d * d;
            d = x0.y - a0.y * inv_m; s += d * d;
            d = x0.z - a0.z * inv_m; s += d * d;
            d = x0.w - a0.w * inv_m; s += d * d;
            d = x1.x - a1.x * inv_m; s += d * d;
            d = x1.y - a1.y * inv_m; s += d * d;
            d = x1.z - a1.z * inv_m; s += d * d;
            d = x1.w - a1.w * inv_m; s += d * d;
            acc += valid ? s : 0.f;
        }
#pragma unroll
        for (int o = 16; o > 0; o >>= 1)
            acc += __shfl_down_sync(0xffffffffu, acc, o);
        rowloss = acc;
    }

    if (lane == 0) {
        float4 s0 = *(const float4*)(scores + (size_t)i * NCLS);
        float4 s1 = *(const float4*)(scores + (size_t)i * NCLS + 4);
        float sv[8] = {s0.x, s0.y, s0.z, s0.w, s1.x, s1.y, s1.z, s1.w};
        float mx = sv[0];
#pragma unroll
        for (int c = 1; c < 8; c++) mx = fmaxf(mx, sv[c]);
        float se = 0.f;
#pragma unroll
        for (int c = 0; c < 8; c++) se += __expf(sv[c] - mx);
        float ce = (mx + __logf(se)) - sv[cls];
        s_part[warp] = ce * (1.0f / (float)N) + 25.0f * rowloss;  // LAM*0.5 = 25
    }
    __syncthreads();

    if (threadIdx.x == 0) {
        float p = 0.f;
#pragma unroll
        for (int w = 0; w < 8; w++) p += s_part[w];
        g_partial[blockIdx.x] = p;
        __threadfence();
        unsigned int done = atomicAdd(&g_counter, 1u);
        s_last = (done == 255u);
    }
    __syncthreads();

    if (s_last) {
        __shared__ float sred[256];
        int t = threadIdx.x;
        sred[t] = g_partial[t];
        __syncthreads();
        for (int o = 128; o > 0; o >>= 1) {
            if (t < o) sred[t] += sred[t + o];
            __syncthreads();
        }
        if (t == 0) out[0] = sred[0];
    }
}

// ---------------------------------------------------------------------------
extern "C" void kernel_launch(void* const* d_in, const int* in_sizes, int n_in,
                              void* d_out, int out_size) {
    const float* feature = (const float*)d_in[0];   // [2048, 256]
    const float* scores  = (const float*)d_in[1];   // [2048, 8]
    const int*   target  = (const int*)d_in[2];     // [2048]
    float* out = (float*)d_out;

    dist_kernel<<<672, 256>>>(feature, target);
    topk_loss_kernel<<<N / 8, 256>>>(feature, scores, target, out);
}

// round 13
// speedup vs baseline: 1.2214x; 1.0200x over previous
#include <cuda_runtime.h>
#include <cuda_bf16.h>
#include <math.h>

// Problem shape (fixed by setup_inputs)
#define N     2048
#define C     256
#define NCLS  8
#define KSEL  20
#define MAXC  384      // class size bound; tiles cover 6*64=384
#define EPS   1e-6f

typedef unsigned long long u64;

// Scratch (static __device__ — no allocations)
// g_D layout: [4 channel-quarters][N rows (original index)][MAXC positions]
__device__ float g_D[4ull * N * MAXC];
__device__ int   g_orderC[NCLS * MAXC];   // per-class member lists (original indices)
__device__ int   g_cntC[NCLS];
__device__ float g_partial[256];
__device__ unsigned int g_counter;

// triangle tile enumeration: x >= y, 6x6 -> 21 tiles
__device__ __constant__ int c_tx[21] = {0,1,1,2,2,2,3,3,3,3,4,4,4,4,4,5,5,5,5,5,5};
__device__ __constant__ int c_ty[21] = {0,0,1,0,1,2,0,1,2,3,0,1,2,3,4,0,1,2,3,4,5};

__device__ __forceinline__ float finf() { return __int_as_float(0x7f800000); }

__device__ __forceinline__ u64 addx2(u64 a, u64 b) {
    u64 r;
    asm("add.rn.f32x2 %0, %1, %2;" : "=l"(r) : "l"(a), "l"(b));
    return r;
}

// ---------------------------------------------------------------------------
// Kernel 1: class-blocked pairwise L1 (no eps -> symmetric), channel-quarter
// split, TRIANGLE tiles only (x >= y), mirror store via smem transpose.
// Inline per-block class-list rebuild; publishers (cs==0, e==0) export lists.
// Grid: 672 = 4 quarters x 8 classes x 21 triangle tiles.
// (EXACT structure of the measured-best R11 kernel.)
// ---------------------------------------------------------------------------
#define TB 64
#define KC 64      // channels per chunk == quarter size (32 packed pairs)
#define PADTB 66   // padded row length (528 bytes, multiple of 16)

__global__ __launch_bounds__(256, 3)
void dist_kernel(const float* __restrict__ feat, const int* __restrict__ target) {
    int bid = blockIdx.x;
    if (bid == 0 && threadIdx.x == 0) g_counter = 0u;   // reset for topk

    int cs  = bid / 168;               // channel quarter 0..3
    int b   = bid - cs * 168;
    int cls = b / 21;
    int e   = b - cls * 21;
    int x = c_tx[e], y = c_ty[e];      // x >= y

    __shared__ __align__(16) float As2[KC / 2][PADTB][2];   // a, pair packed
    __shared__ __align__(16) float Bs2[KC / 2][PADTB][2];   // -b, pair packed
    __shared__ __align__(16) int   list[MAXC];
    __shared__ int   s_wofs[8];
    __shared__ int   s_cnt;

    int t    = threadIdx.x;
    int lane = t & 31;
    int w    = t >> 5;

    // ---- cheap count first: early-exit for non-working tiles ----
    int4 t0 = *(const int4*)(target + t * 8);
    int4 t1 = *(const int4*)(target + t * 8 + 4);
    int tg[8] = {t0.x, t0.y, t0.z, t0.w, t1.x, t1.y, t1.z, t1.w};
    int mcount = 0;
#pragma unroll
    for (int u = 0; u < 8; u++) mcount += (tg[u] == cls);

    int red = mcount;
#pragma unroll
    for (int o = 16; o > 0; o >>= 1) red += __shfl_down_sync(0xffffffffu, red, o);
    if (lane == 0) s_wofs[w] = red;
    __syncthreads();
    if (t == 0) {
        int acc = 0;
#pragma unroll
        for (int ww = 0; ww < 8; ww++) acc += s_wofs[ww];
        s_cnt = acc;
    }
    __syncthreads();
    int cnt = min(s_cnt, MAXC);

    int ti0 = y * TB;
    int tj0 = x * TB;
    if (ti0 >= cnt || tj0 >= cnt) return;   // publishers (e==0) always pass

    // ---- full stable compaction (working blocks only) ----
    int incl = mcount;
#pragma unroll
    for (int o = 1; o < 32; o <<= 1) {
        int v = __shfl_up_sync(0xffffffffu, incl, o);
        if (lane >= o) incl += v;
    }
    if (lane == 31) s_wofs[w] = incl;
    __syncthreads();
    if (t == 0) {
        int acc = 0;
#pragma unroll
        for (int ww = 0; ww < 8; ww++) { int v = s_wofs[ww]; s_wofs[ww] = acc; acc += v; }
    }
    __syncthreads();
    int base = s_wofs[w] + incl - mcount;   // exclusive prefix for this thread
#pragma unroll
    for (int u = 0; u < 8; u++) {
        if (tg[u] == cls && base < MAXC) { list[base] = t * 8 + u; base++; }
    }
    __syncthreads();
    for (int p = cnt + t; p < MAXC; p += 256) list[p] = 0;   // safe padding
    __syncthreads();

    // publisher blocks export the list for topk (one block per class)
    if (cs == 0 && e == 0) {
        if (t == 0) g_cntC[cls] = cnt;
        for (int p = t; p < MAXC; p += 256) g_orderC[cls * MAXC + p] = list[p];
    }

    // ---- staging: thread t fills column lr, 16 channels ----
    {
        int lr = t & 63;
        int lc = (t >> 6) * 16;       // 0,16,32,48
        int gi = ti0 + lr, gj = tj0 + lr;
        const float* arow = feat + (size_t)list[min(gi, MAXC - 1)] * C;
        const float* brow = feat + (size_t)list[min(gj, MAXC - 1)] * C;
        int cc = cs * 64 + lc;
        int p0 = lc >> 1;
#pragma unroll
        for (int q = 0; q < 4; q++) {
            float4 pa = *(const float4*)(arow + cc + q * 4);
            float4 pb = *(const float4*)(brow + cc + q * 4);
            *(float2*)&As2[p0 + 2 * q + 0][lr][0] = make_float2(pa.x, pa.y);
            *(float2*)&As2[p0 + 2 * q + 1][lr][0] = make_float2(pa.z, pa.w);
            *(float2*)&Bs2[p0 + 2 * q + 0][lr][0] = make_float2(-pb.x, -pb.y);
            *(float2*)&Bs2[p0 + 2 * q + 1][lr][0] = make_float2(-pb.z, -pb.w);
        }
    }
    __syncthreads();

    int tx = t & 15;      // j columns: tx + 16c
    int ty = t >> 4;      // i rows: ty*4 + ii

    u64 acc2[16];
#pragma unroll
    for (int q = 0; q < 16; q++) acc2[q] = 0ull;

#pragma unroll
    for (int kk2 = 0; kk2 < KC / 2; kk2++) {
        ulonglong2 aL = *(const ulonglong2*)&As2[kk2][ty * 4][0];
        ulonglong2 aH = *(const ulonglong2*)&As2[kk2][ty * 4 + 2][0];
        u64 a2[4] = {aL.x, aL.y, aH.x, aH.y};
        u64 b2[4];
#pragma unroll
        for (int c = 0; c < 4; c++)
            b2[c] = *(const u64*)&Bs2[kk2][tx + c * 16][0];
#pragma unroll
        for (int ii = 0; ii < 4; ii++)
#pragma unroll
            for (int c = 0; c < 4; c++) {
                u64 d = addx2(a2[ii], b2[c]);           // a - b
                d &= 0x7FFFFFFF7FFFFFFFull;             // packed |.|
                acc2[ii * 4 + c] = addx2(acc2[ii * 4 + c], d);
            }
    }

    // unpack results
    float res[4][4];
#pragma unroll
    for (int ii = 0; ii < 4; ii++)
#pragma unroll
        for (int c = 0; c < 4; c++) {
            u64 a = acc2[ii * 4 + c];
            float lo = __uint_as_float((unsigned)(a & 0xFFFFFFFFull));
            float hi = __uint_as_float((unsigned)(a >> 32));
            res[ii][c] = lo + hi;
        }

    float* dq = g_D + (size_t)cs * N * MAXC;

    // direct store: D[list[ti]][tj0 + tx + 16c]
#pragma unroll
    for (int ii = 0; ii < 4; ii++) {
        int ti = ti0 + ty * 4 + ii;
        if (ti >= cnt) continue;
        float* dr = dq + (size_t)list[ti] * MAXC + tj0;
#pragma unroll
        for (int c = 0; c < 4; c++) {
            int tj = tj0 + tx + c * 16;
            dr[tx + c * 16] = (ti == tj) ? finf() : res[ii][c];
        }
    }

    // mirror store for off-diagonal tiles (transpose via smem alias of As2)
    if (x != y) {
        __syncthreads();   // mainloop reads done before overwriting As2
        float* tb = &As2[0][0][0];   // 64 x 65 floats fits in As2
#pragma unroll
        for (int ii = 0; ii < 4; ii++)
#pragma unroll
            for (int c = 0; c < 4; c++)
                tb[(ty * 4 + ii) * 65 + tx + c * 16] = res[ii][c];
        __syncthreads();

        int j  = t & 63;
        int ic = (t >> 6) * 16;
        if (tj0 + j < cnt) {
            float* drj = dq + (size_t)list[tj0 + j] * MAXC + ti0 + ic;
#pragma unroll
            for (int q = 0; q < 4; q++) {
                float4 o;
                o.x = tb[(ic + 4 * q + 0) * 65 + j];
                o.y = tb[(ic + 4 * q + 1) * 65 + j];
                o.z = tb[(ic + 4 * q + 2) * 65 + j];
                o.w = tb[(ic + 4 * q + 3) * 65 + j];
                *(float4*)(drj + 4 * q) = o;
            }
        }
    }
}

// ---------------------------------------------------------------------------
// Kernel 2: fused top-K + neighbor MSE + CE + final reduction (last block).
// One warp per row. NEW selection core: tournament-tree local two-smallest
// (parallel, ~40cyc) + REDUX.MIN warp reduction (2 instrs, result in all
// lanes, no broadcast shfls). Round chain ~125cyc vs ~400 before.
// ---------------------------------------------------------------------------
__device__ __forceinline__ unsigned tree_min12(const unsigned* v) {
    unsigned t0 = min(v[0], v[1]),  t1 = min(v[2], v[3]);
    unsigned t2 = min(v[4], v[5]),  t3 = min(v[6], v[7]);
    unsigned t4 = min(v[8], v[9]),  t5 = min(v[10], v[11]);
    unsigned u0 = min(t0, t1), u1 = min(t2, t3), u2 = min(t4, t5);
    return min(min(u0, u1), u2);
}

__global__ __launch_bounds__(256, 2)
void topk_loss_kernel(const float* __restrict__ feat,
                      const float* __restrict__ scores,
                      const int* __restrict__ target,
                      float* __restrict__ out) {
    __shared__ float s_part[8];
    __shared__ bool  s_last;

    int warp = threadIdx.x >> 5;
    int lane = threadIdx.x & 31;
    int i = blockIdx.x * 8 + warp;

    int cls = target[i];
    int cnt = min(g_cntC[cls], MAXC);
    const int* order = g_orderC + cls * MAXC;
    int m = min(cnt - 1, KSEL);

    float rowloss = 0.f;
    if (m > 0) {
        const float* d0 = g_D + (size_t)i * MAXC;
        const float* d1 = g_D + (size_t)(N + i) * MAXC;
        const float* d2 = g_D + (size_t)(2 * N + i) * MAXC;
        const float* d3 = g_D + (size_t)(3 * N + i) * MAXC;

        // packed keys: high 23 bits of distance | 9-bit position (unique)
        unsigned v[12];
#pragma unroll
        for (int s = 0; s < 12; s++) {
            int p = s * 32 + lane;
            if (p < cnt) {
                float d = (d0[p] + d1[p]) + (d2[p] + d3[p]);
                v[s] = (__float_as_uint(d) & 0xFFFFFE00u) | (unsigned)p;
            } else {
                v[s] = 0xFFFFFFFFu;
            }
        }

        unsigned mypos = 511u;
#pragma unroll
        for (int r = 0; r < 10; r++) {
            // local two smallest via tournament trees (parallel, short chain)
            unsigned k1 = tree_min12(v);
            unsigned wv[12];
#pragma unroll
            for (int s = 0; s < 12; s++)
                wv[s] = (v[s] == k1) ? 0xFFFFFFFFu : v[s];
            unsigned k2 = tree_min12(wv);

            // warp two smallest via REDUX (result uniform across lanes)
            unsigned g1 = __reduce_min_sync(0xffffffffu, k1);
            unsigned cand = (k1 == g1) ? k2 : k1;
            unsigned g2 = __reduce_min_sync(0xffffffffu, cand);

            if (lane == 2 * r)     mypos = g1 & 511u;
            if (lane == 2 * r + 1) mypos = g2 & 511u;
#pragma unroll
            for (int s = 0; s < 12; s++) {
                if (v[s] == g1 || v[s] == g2) v[s] = 0xFFFFFFFFu;
            }
        }

        // resolve neighbor original index per lane (20 parallel loads)
        unsigned cp = min(mypos, (unsigned)(MAXC - 1));
        int myj = order[cp];

        // MSE gather: lane owns 8 channels; pre-resolved j broadcast per k.
        float inv_m = 1.0f / (float)m;
        const float* xi = feat + (size_t)i * C + lane * 8;
        float4 x0 = *(const float4*)(xi);
        float4 x1 = *(const float4*)(xi + 4);
        float acc = 0.f;
#pragma unroll
        for (int k = 0; k < KSEL; k++) {
            bool valid = (k < m);
            int j = __shfl_sync(0xffffffffu, myj, k);
            const float* xj = feat + (size_t)j * C + lane * 8;
            float4 a0 = *(const float4*)(xj);
            float4 a1 = *(const float4*)(xj + 4);
            float s = 0.f, d;
            d = x0.x - a0.x * inv_m; s += d * d;
            d = x0.y - a0.y * inv_m; s += d * d;
            d = x0.z - a0.z * inv_m; s += d * d;
            d = x0.w - a0.w * inv_m; s += d * d;
            d = x1.x - a1.x * inv_m; s += d * d;
            d = x1.y - a1.y * inv_m; s += d * d;
            d = x1.z - a1.z * inv_m; s += d * d;
            d = x1.w - a1.w * inv_m; s += d * d;
            acc += valid ? s : 0.f;
        }
#pragma unroll
        for (int o = 16; o > 0; o >>= 1)
            acc += __shfl_down_sync(0xffffffffu, acc, o);
        rowloss = acc;
    }

    if (lane == 0) {
        float4 s0 = *(const float4*)(scores + (size_t)i * NCLS);
        float4 s1 = *(const float4*)(scores + (size_t)i * NCLS + 4);
        float sv[8] = {s0.x, s0.y, s0.z, s0.w, s1.x, s1.y, s1.z, s1.w};
        float mx = sv[0];
#pragma unroll
        for (int c = 1; c < 8; c++) mx = fmaxf(mx, sv[c]);
        float se = 0.f;
#pragma unroll
        for (int c = 0; c < 8; c++) se += __expf(sv[c] - mx);
        float ce = (mx + __logf(se)) - sv[cls];
        s_part[warp] = ce * (1.0f / (float)N) + 25.0f * rowloss;  // LAM*0.5 = 25
    }
    __syncthreads();

    if (threadIdx.x == 0) {
        float p = 0.f;
#pragma unroll
        for (int w = 0; w < 8; w++) p += s_part[w];
        g_partial[blockIdx.x] = p;
        __threadfence();
        unsigned int done = atomicAdd(&g_counter, 1u);
        s_last = (done == 255u);
    }
    __syncthreads();

    if (s_last) {
        __shared__ float sred[256];
        int t = threadIdx.x;
        sred[t] = g_partial[t];
        __syncthreads();
        for (int o = 128; o > 0; o >>= 1) {
            if (t < o) sred[t] += sred[t + o];
            __syncthreads();
        }
        if (t == 0) out[0] = sred[0];
    }
}

// ---------------------------------------------------------------------------
extern "C" void kernel_launch(void* const* d_in, const int* in_sizes, int n_in,
                              void* d_out, int out_size) {
    const float* feature = (const float*)d_in[0];   // [2048, 256]
    const float* scores  = (const float*)d_in[1];   // [2048, 8]
    const int*   target  = (const int*)d_in[2];     // [2048]
    float* out = (float*)d_out;

    dist_kernel<<<672, 256>>>(feature, target);
    topk_loss_kernel<<<N / 8, 256>>>(feature, scores, target, out);
}

// round 14
// speedup vs baseline: 1.2598x; 1.0315x over previous
#include <cuda_runtime.h>
#include <cuda_bf16.h>
#include <math.h>

// Problem shape (fixed by setup_inputs)
#define N     2048
#define C     256
#define NCLS  8
#define KSEL  20
#define MAXC  384      // class size bound; tiles cover 6*64=384; = 32 lanes * 12
#define EPS   1e-6f

typedef unsigned long long u64;

// Scratch (static __device__ — no allocations)
// g_D layout: [4 channel-quarters][N rows (original index)][MAXC positions]
__device__ float g_D[4ull * N * MAXC];
__device__ int   g_orderC[NCLS * MAXC];   // per-class member lists (original indices)
__device__ int   g_cntC[NCLS];
__device__ float g_partial[256];
__device__ unsigned int g_counter;

// triangle tile enumeration: x >= y, 6x6 -> 21 tiles
__device__ __constant__ int c_tx[21] = {0,1,1,2,2,2,3,3,3,3,4,4,4,4,4,5,5,5,5,5,5};
__device__ __constant__ int c_ty[21] = {0,0,1,0,1,2,0,1,2,3,0,1,2,3,4,0,1,2,3,4,5};

__device__ __forceinline__ float finf() { return __int_as_float(0x7f800000); }

__device__ __forceinline__ u64 addx2(u64 a, u64 b) {
    u64 r;
    asm("add.rn.f32x2 %0, %1, %2;" : "=l"(r) : "l"(a), "l"(b));
    return r;
}

// ---------------------------------------------------------------------------
// Kernel 1: class-blocked pairwise L1 (no eps -> symmetric), channel-quarter
// split, TRIANGLE tiles only (x >= y), mirror store via smem transpose.
// j-columns per thread: {2tx, 2tx+1, 32+2tx, 32+2tx+1} -> B loads are
// 2x LDS.128 (conflict-free) and direct stores are float2.
// Grid: 672 = 4 quarters x 8 classes x 21 triangle tiles.
// ---------------------------------------------------------------------------
#define TB 64
#define KC 64      // channels per chunk == quarter size (32 packed pairs)
#define PADTB 66   // padded row length (528 bytes, multiple of 16)

__global__ __launch_bounds__(256, 3)
void dist_kernel(const float* __restrict__ feat, const int* __restrict__ target) {
    int bid = blockIdx.x;
    if (bid == 0 && threadIdx.x == 0) g_counter = 0u;   // reset for topk

    int cs  = bid / 168;               // channel quarter 0..3
    int b   = bid - cs * 168;
    int cls = b / 21;
    int e   = b - cls * 21;
    int x = c_tx[e], y = c_ty[e];      // x >= y

    __shared__ __align__(16) float As2[KC / 2][PADTB][2];   // a, pair packed
    __shared__ __align__(16) float Bs2[KC / 2][PADTB][2];   // -b, pair packed
    __shared__ __align__(16) int   list[MAXC];
    __shared__ int   s_wofs[8];
    __shared__ int   s_cnt;

    int t    = threadIdx.x;
    int lane = t & 31;
    int w    = t >> 5;

    // ---- cheap count first: early-exit for non-working tiles ----
    int4 t0 = *(const int4*)(target + t * 8);
    int4 t1 = *(const int4*)(target + t * 8 + 4);
    int tg[8] = {t0.x, t0.y, t0.z, t0.w, t1.x, t1.y, t1.z, t1.w};
    int mcount = 0;
#pragma unroll
    for (int u = 0; u < 8; u++) mcount += (tg[u] == cls);

    int red = mcount;
#pragma unroll
    for (int o = 16; o > 0; o >>= 1) red += __shfl_down_sync(0xffffffffu, red, o);
    if (lane == 0) s_wofs[w] = red;
    __syncthreads();
    if (t == 0) {
        int acc = 0;
#pragma unroll
        for (int ww = 0; ww < 8; ww++) acc += s_wofs[ww];
        s_cnt = acc;
    }
    __syncthreads();
    int cnt = min(s_cnt, MAXC);

    int ti0 = y * TB;
    int tj0 = x * TB;
    if (ti0 >= cnt || tj0 >= cnt) return;   // publishers (e==0) always pass

    // ---- full stable compaction (working blocks only) ----
    int incl = mcount;
#pragma unroll
    for (int o = 1; o < 32; o <<= 1) {
        int v = __shfl_up_sync(0xffffffffu, incl, o);
        if (lane >= o) incl += v;
    }
    if (lane == 31) s_wofs[w] = incl;
    __syncthreads();
    if (t == 0) {
        int acc = 0;
#pragma unroll
        for (int ww = 0; ww < 8; ww++) { int v = s_wofs[ww]; s_wofs[ww] = acc; acc += v; }
    }
    __syncthreads();
    int base = s_wofs[w] + incl - mcount;   // exclusive prefix for this thread
#pragma unroll
    for (int u = 0; u < 8; u++) {
        if (tg[u] == cls && base < MAXC) { list[base] = t * 8 + u; base++; }
    }
    __syncthreads();
    for (int p = cnt + t; p < MAXC; p += 256) list[p] = 0;   // safe padding
    __syncthreads();

    // publisher blocks export the list for topk (one block per class)
    if (cs == 0 && e == 0) {
        if (t == 0) g_cntC[cls] = cnt;
        for (int p = t; p < MAXC; p += 256) g_orderC[cls * MAXC + p] = list[p];
    }

    // ---- staging: thread t fills column lr, 16 channels ----
    {
        int lr = t & 63;
        int lc = (t >> 6) * 16;       // 0,16,32,48
        int gi = ti0 + lr, gj = tj0 + lr;
        const float* arow = feat + (size_t)list[min(gi, MAXC - 1)] * C;
        const float* brow = feat + (size_t)list[min(gj, MAXC - 1)] * C;
        int cc = cs * 64 + lc;
        int p0 = lc >> 1;
#pragma unroll
        for (int q = 0; q < 4; q++) {
            float4 pa = *(const float4*)(arow + cc + q * 4);
            float4 pb = *(const float4*)(brow + cc + q * 4);
            *(float2*)&As2[p0 + 2 * q + 0][lr][0] = make_float2(pa.x, pa.y);
            *(float2*)&As2[p0 + 2 * q + 1][lr][0] = make_float2(pa.z, pa.w);
            *(float2*)&Bs2[p0 + 2 * q + 0][lr][0] = make_float2(-pb.x, -pb.y);
            *(float2*)&Bs2[p0 + 2 * q + 1][lr][0] = make_float2(-pb.z, -pb.w);
        }
    }
    __syncthreads();

    int tx = t & 15;      // j columns: {2tx, 2tx+1, 32+2tx, 32+2tx+1}
    int ty = t >> 4;      // i rows: ty*4 + ii

    u64 acc2[16];
#pragma unroll
    for (int q = 0; q < 16; q++) acc2[q] = 0ull;

#pragma unroll
    for (int kk2 = 0; kk2 < KC / 2; kk2++) {
        ulonglong2 aL = *(const ulonglong2*)&As2[kk2][ty * 4][0];
        ulonglong2 aH = *(const ulonglong2*)&As2[kk2][ty * 4 + 2][0];
        u64 a2[4] = {aL.x, aL.y, aH.x, aH.y};
        ulonglong2 bL = *(const ulonglong2*)&Bs2[kk2][2 * tx][0];       // cols 2tx,2tx+1
        ulonglong2 bH = *(const ulonglong2*)&Bs2[kk2][32 + 2 * tx][0];  // cols 32+2tx,+1
        u64 b2[4] = {bL.x, bL.y, bH.x, bH.y};
#pragma unroll
        for (int ii = 0; ii < 4; ii++)
#pragma unroll
            for (int c = 0; c < 4; c++) {
                u64 d = addx2(a2[ii], b2[c]);           // a - b
                d &= 0x7FFFFFFF7FFFFFFFull;             // packed |.|
                acc2[ii * 4 + c] = addx2(acc2[ii * 4 + c], d);
            }
    }

    // unpack results; res column c -> tile col (c>>1)*32 + 2tx + (c&1)
    float res[4][4];
#pragma unroll
    for (int ii = 0; ii < 4; ii++)
#pragma unroll
        for (int c = 0; c < 4; c++) {
            u64 a = acc2[ii * 4 + c];
            float lo = __uint_as_float((unsigned)(a & 0xFFFFFFFFull));
            float hi = __uint_as_float((unsigned)(a >> 32));
            res[ii][c] = lo + hi;
        }

    float* dq = g_D + (size_t)cs * N * MAXC;

    // direct store: two float2 per row (cols 2tx.. and 32+2tx..)
#pragma unroll
    for (int ii = 0; ii < 4; ii++) {
        int ti = ti0 + ty * 4 + ii;
        if (ti >= cnt) continue;
        float* dr = dq + (size_t)list[ti] * MAXC + tj0;
        float o0 = (ti == tj0 + 2 * tx)          ? finf() : res[ii][0];
        float o1 = (ti == tj0 + 2 * tx + 1)      ? finf() : res[ii][1];
        float o2 = (ti == tj0 + 32 + 2 * tx)     ? finf() : res[ii][2];
        float o3 = (ti == tj0 + 32 + 2 * tx + 1) ? finf() : res[ii][3];
        *(float2*)(dr + 2 * tx)      = make_float2(o0, o1);
        *(float2*)(dr + 32 + 2 * tx) = make_float2(o2, o3);
    }

    // mirror store for off-diagonal tiles (transpose via smem alias of As2)
    if (x != y) {
        __syncthreads();   // mainloop reads done before overwriting As2
        float* tb = &As2[0][0][0];   // 64 x 65 floats fits in As2
#pragma unroll
        for (int ii = 0; ii < 4; ii++)
#pragma unroll
            for (int c = 0; c < 4; c++) {
                int col = (c >> 1) * 32 + 2 * tx + (c & 1);
                tb[(ty * 4 + ii) * 65 + col] = res[ii][c];
            }
        __syncthreads();

        int j  = t & 63;
        int ic = (t >> 6) * 16;
        if (tj0 + j < cnt) {
            float* drj = dq + (size_t)list[tj0 + j] * MAXC + ti0 + ic;
#pragma unroll
            for (int q = 0; q < 4; q++) {
                float4 o;
                o.x = tb[(ic + 4 * q + 0) * 65 + j];
                o.y = tb[(ic + 4 * q + 1) * 65 + j];
                o.z = tb[(ic + 4 * q + 2) * 65 + j];
                o.w = tb[(ic + 4 * q + 3) * 65 + j];
                *(float4*)(drj + 4 * q) = o;
            }
        }
    }
}

// ---------------------------------------------------------------------------
// Kernel 2: fused top-K + neighbor MSE + CE + final reduction (last block).
// One warp per row. Lane owns 12 CONSECUTIVE positions (p = lane*12 + s) so
// each distance quarter is 3x LDG.128 -> 12 vector loads total (was 48 scalar).
// Selection: tournament trees + REDUX.MIN (measured best core).
// ---------------------------------------------------------------------------
__device__ __forceinline__ unsigned tree_min12(const unsigned* v) {
    unsigned t0 = min(v[0], v[1]),  t1 = min(v[2], v[3]);
    unsigned t2 = min(v[4], v[5]),  t3 = min(v[6], v[7]);
    unsigned t4 = min(v[8], v[9]),  t5 = min(v[10], v[11]);
    unsigned u0 = min(t0, t1), u1 = min(t2, t3), u2 = min(t4, t5);
    return min(min(u0, u1), u2);
}

__global__ __launch_bounds__(256, 2)
void topk_loss_kernel(const float* __restrict__ feat,
                      const float* __restrict__ scores,
                      const int* __restrict__ target,
                      float* __restrict__ out) {
    __shared__ float s_part[8];
    __shared__ bool  s_last;

    int warp = threadIdx.x >> 5;
    int lane = threadIdx.x & 31;
    int i = blockIdx.x * 8 + warp;

    int cls = target[i];
    int cnt = min(g_cntC[cls], MAXC);
    const int* order = g_orderC + cls * MAXC;
    int m = min(cnt - 1, KSEL);

    float rowloss = 0.f;
    if (m > 0) {
        int pbase = lane * 12;
        const float4* d0 = (const float4*)(g_D + (size_t)i * MAXC + pbase);
        const float4* d1 = (const float4*)(g_D + (size_t)(N + i) * MAXC + pbase);
        const float4* d2 = (const float4*)(g_D + (size_t)(2 * N + i) * MAXC + pbase);
        const float4* d3 = (const float4*)(g_D + (size_t)(3 * N + i) * MAXC + pbase);

        float sum[12];
#pragma unroll
        for (int q = 0; q < 3; q++) {
            float4 a = d0[q], b = d1[q], c = d2[q], dd = d3[q];
            sum[4 * q + 0] = (a.x + b.x) + (c.x + dd.x);
            sum[4 * q + 1] = (a.y + b.y) + (c.y + dd.y);
            sum[4 * q + 2] = (a.z + b.z) + (c.z + dd.z);
            sum[4 * q + 3] = (a.w + b.w) + (c.w + dd.w);
        }

        // packed keys: high 23 bits of distance | 9-bit position (unique)
        unsigned v[12];
#pragma unroll
        for (int s = 0; s < 12; s++) {
            int p = pbase + s;
            v[s] = (p < cnt)
                 ? ((__float_as_uint(sum[s]) & 0xFFFFFE00u) | (unsigned)p)
                 : 0xFFFFFFFFu;
        }

        unsigned mypos = 511u;
#pragma unroll
        for (int r = 0; r < 10; r++) {
            unsigned k1 = tree_min12(v);
            unsigned wv[12];
#pragma unroll
            for (int s = 0; s < 12; s++)
                wv[s] = (v[s] == k1) ? 0xFFFFFFFFu : v[s];
            unsigned k2 = tree_min12(wv);

            unsigned g1 = __reduce_min_sync(0xffffffffu, k1);
            unsigned cand = (k1 == g1) ? k2 : k1;
            unsigned g2 = __reduce_min_sync(0xffffffffu, cand);

            if (lane == 2 * r)     mypos = g1 & 511u;
            if (lane == 2 * r + 1) mypos = g2 & 511u;
#pragma unroll
            for (int s = 0; s < 12; s++) {
                if (v[s] == g1 || v[s] == g2) v[s] = 0xFFFFFFFFu;
            }
        }

        // resolve neighbor original index per lane (20 parallel loads)
        unsigned cp = min(mypos, (unsigned)(MAXC - 1));
        int myj = order[cp];

        // MSE gather: lane owns 8 channels; pre-resolved j broadcast per k.
        float inv_m = 1.0f / (float)m;
        const float* xi = feat + (size_t)i * C + lane * 8;
        float4 x0 = *(const float4*)(xi);
        float4 x1 = *(const float4*)(xi + 4);
        float acc = 0.f;
#pragma unroll
        for (int k = 0; k < KSEL; k++) {
            bool valid = (k < m);
            int j = __shfl_sync(0xffffffffu, myj, k);
            const float* xj = feat + (size_t)j * C + lane * 8;
            float4 a0 = *(const float4*)(xj);
            float4 a1 = *(const float4*)(xj + 4);
            float s = 0.f, d;
            d = x0.x - a0.x * inv_m; s += d * d;
            d = x0.y - a0.y * inv_m; s += d * d;
            d = x0.z - a0.z * inv_m; s += d * d;
            d = x0.w - a0.w * inv_m; s += d * d;
            d = x1.x - a1.x * inv_m; s += d * d;
            d = x1.y - a1.y * inv_m; s += d * d;
            d = x1.z - a1.z * inv_m; s += d * d;
            d = x1.w - a1.w * inv_m; s += d * d;
            acc += valid ? s : 0.f;
        }
#pragma unroll
        for (int o = 16; o > 0; o >>= 1)
            acc += __shfl_down_sync(0xffffffffu, acc, o);
        rowloss = acc;
    }

    if (lane == 0) {
        float4 s0 = *(const float4*)(scores + (size_t)i * NCLS);
        float4 s1 = *(const float4*)(scores + (size_t)i * NCLS + 4);
        float sv[8] = {s0.x, s0.y, s0.z, s0.w, s1.x, s1.y, s1.z, s1.w};
        float mx = sv[0];
#pragma unroll
        for (int c = 1; c < 8; c++) mx = fmaxf(mx, sv[c]);
        float se = 0.f;
#pragma unroll
        for (int c = 0; c < 8; c++) se += __expf(sv[c] - mx);
        float ce = (mx + __logf(se)) - sv[cls];
        s_part[warp] = ce * (1.0f / (float)N) + 25.0f * rowloss;  // LAM*0.5 = 25
    }
    __syncthreads();

    if (threadIdx.x == 0) {
        float p = 0.f;
#pragma unroll
        for (int w = 0; w < 8; w++) p += s_part[w];
        g_partial[blockIdx.x] = p;
        __threadfence();
        unsigned int done = atomicAdd(&g_counter, 1u);
        s_last = (done == 255u);
    }
    __syncthreads();

    if (s_last) {
        __shared__ float sred[256];
        int t = threadIdx.x;
        sred[t] = g_partial[t];
        __syncthreads();
        for (int o = 128; o > 0; o >>= 1) {
            if (t < o) sred[t] += sred[t + o];
            __syncthreads();
        }
        if (t == 0) out[0] = sred[0];
    }
}

// ---------------------------------------------------------------------------
extern "C" void kernel_launch(void* const* d_in, const int* in_sizes, int n_in,
                              void* d_out, int out_size) {
    const float* feature = (const float*)d_in[0];   // [2048, 256]
    const float* scores  = (const float*)d_in[1];   // [2048, 8]
    const int*   target  = (const int*)d_in[2];     // [2048]
    float* out = (float*)d_out;

    dist_kernel<<<672, 256>>>(feature, target);
    topk_loss_kernel<<<N / 8, 256>>>(feature, scores, target, out);
}